// round 14
// baseline (speedup 1.0000x reference)
#include <cuda_runtime.h>
#include <cuda_bf16.h>
#include <cstdint>

// LorenzSDE ShARK integrator, B = 4,194,304, 5 steps, additive noise.
// HBM-bound streaming (604 MB) at ~6.7 TB/s (~84-85% DRAM). At the
// efficiency plateau; this round trims per-CTA overhead:
//  - x staged via float4 (1 L1 wavefront/load vs 12 for stride-3 LDG.32)
//  - dedicated s_o output buffer -> 2 barriers instead of 3
//  - proven config: 128-thr CTAs, 12/SM, __ldcs/__stcs streaming hints

#define BATCH_TOTAL 4194304
#define NSTEP 5
#define TILE 128                       // batch elements per tile == threads
#define BLK 128
#define NTILES (BATCH_TOTAL / TILE)    // 32768

__device__ __forceinline__ void lorenz_drift(float x, float y, float z,
                                             float& fx, float& fy, float& fz) {
    fx = 10.0f * (y - x);
    fy = x * (28.0f - z) - y;
    fz = x * y - (8.0f / 3.0f) * z;
}

__global__ __launch_bounds__(BLK, 12)
void lorenz_shark_kernel(const float* __restrict__ x,
                         const float* __restrict__ dW,
                         const float* __restrict__ dH,
                         float* __restrict__ out) {
    __shared__ __align__(16) float s_w[TILE * 15];   // 7680 B
    __shared__ __align__(16) float s_h[TILE * 15];   // 7680 B
    __shared__ __align__(16) float s_x[TILE * 3];    // 1536 B
    __shared__ __align__(16) float s_o[TILE * 3];    // 1536 B

    const int tid = threadIdx.x;
    const size_t base = (size_t)blockIdx.x * TILE;

    // ---- coalesced float4 staging: dW/dH (480 float4 each), x (96) -----
    const float4* __restrict__ w4 = (const float4*)(dW + base * 15);
    const float4* __restrict__ h4 = (const float4*)(dH + base * 15);
    const float4* __restrict__ x4 = (const float4*)(x  + base * 3);
    float4* sw4 = (float4*)s_w;
    float4* sh4 = (float4*)s_h;
    float4* sx4 = (float4*)s_x;
#pragma unroll
    for (int i = 0; i < 3; i++) {
        sw4[tid + i * BLK] = __ldcs(&w4[tid + i * BLK]);
        sh4[tid + i * BLK] = __ldcs(&h4[tid + i * BLK]);
    }
    if (tid < 96) {                                  // tails: 96 float4 each
        sw4[tid + 3 * BLK] = __ldcs(&w4[tid + 3 * BLK]);
        sh4[tid + 3 * BLK] = __ldcs(&h4[tid + 3 * BLK]);
        sx4[tid]           = __ldcs(&x4[tid]);
    }
    __syncthreads();

    // Per-thread state; stride-3 smem reads (3 coprime 32: conflict-free).
    float y0 = s_x[tid * 3 + 0];
    float y1 = s_x[tid * 3 + 1];
    float y2 = s_x[tid * 3 + 2];

    const float dt    = 0.01f;
    const float cW    = 0.2f;            // NOISE * sqrt(dt)
    const float cH    = 0.057735026919f; // NOISE * sqrt(dt/12)
    const float c56dt = (5.0f / 6.0f) * 0.01f;
    const float c56   = 5.0f / 6.0f;

#pragma unroll
    for (int s = 0; s < NSTEP; s++) {
        const int wb = tid * (NSTEP * 3) + s * 3;    // stride 15: conflict-free
        float w0 = cW * s_w[wb + 0];
        float w1 = cW * s_w[wb + 1];
        float w2 = cW * s_w[wb + 2];
        float h0 = cH * s_h[wb + 0];
        float h1 = cH * s_h[wb + 1];
        float h2 = cH * s_h[wb + 2];

        // z1 = y + h
        float z0 = y0 + h0, z1 = y1 + h1, z2 = y2 + h2;
        float f10, f11, f12;
        lorenz_drift(z0, z1, z2, f10, f11, f12);

        // z2 = y + (5/6)dt*f1 + (5/6)*w + h
        float u0 = y0 + c56dt * f10 + c56 * w0 + h0;
        float u1 = y1 + c56dt * f11 + c56 * w1 + h1;
        float u2 = y2 + c56dt * f12 + c56 * w2 + h2;
        float f20, f21, f22;
        lorenz_drift(u0, u1, u2, f20, f21, f22);

        // y = y + dt*(0.4*f1 + 0.6*f2) + w
        y0 = y0 + dt * (0.4f * f10 + 0.6f * f20) + w0;
        y1 = y1 + dt * (0.4f * f11 + 0.6f * f21) + w1;
        y2 = y2 + dt * (0.4f * f12 + 0.6f * f22) + w2;
    }

    // ---- output via dedicated s_o: no prior readers, no pre-sync needed
    s_o[tid * 3 + 0] = y0;
    s_o[tid * 3 + 1] = y1;
    s_o[tid * 3 + 2] = y2;
    __syncthreads();

    float4* o4 = (float4*)(out + base * 3);
    if (tid < 96)                                    // 96 float4
        __stcs(&o4[tid], ((const float4*)s_o)[tid]);
}

extern "C" void kernel_launch(void* const* d_in, const int* in_sizes, int n_in,
                              void* d_out, int out_size) {
    const float* x  = (const float*)d_in[0];   // [B, 3]
    const float* dW = (const float*)d_in[1];   // [B, 5, 3]
    const float* dH = (const float*)d_in[2];   // [B, 5, 3]
    float* out = (float*)d_out;                // [B, 3]

    lorenz_shark_kernel<<<NTILES, BLK>>>(x, dW, dH, out);
}

// round 15
// speedup vs baseline: 1.1586x; 1.1586x over previous
#include <cuda_runtime.h>
#include <cuda_bf16.h>
#include <cstdint>

// LorenzSDE ShARK integrator, B = 4,194,304, 5 steps, additive noise.
// HBM-bound streaming (604 MB) at ~6.7 TB/s. Proven config (R13):
// 128-thr one-shot CTAs, 12/SM, smem 15.4KB/CTA (keeps ~44KB L1D -- going
// to 18.4KB/CTA starved L1 to 7KB and cost 15 DRAM pts), direct stride-3
// x loads, __ldcs/__stcs. Delta vs R13: output staged into each thread's
// OWN exclusive stride-15 s_w slots -> one barrier removed (3 -> 2).

#define BATCH_TOTAL 4194304
#define NSTEP 5
#define TILE 128                       // batch elements per tile == threads
#define BLK 128
#define NTILES (BATCH_TOTAL / TILE)    // 32768

__device__ __forceinline__ void lorenz_drift(float x, float y, float z,
                                             float& fx, float& fy, float& fz) {
    fx = 10.0f * (y - x);
    fy = x * (28.0f - z) - y;
    fz = x * y - (8.0f / 3.0f) * z;
}

__global__ __launch_bounds__(BLK, 12)
void lorenz_shark_kernel(const float* __restrict__ x,
                         const float* __restrict__ dW,
                         const float* __restrict__ dH,
                         float* __restrict__ out) {
    __shared__ __align__(16) float s_w[TILE * 15];   // 7680 B
    __shared__ __align__(16) float s_h[TILE * 15];   // 7680 B

    const int tid = threadIdx.x;
    const size_t base = (size_t)blockIdx.x * TILE;

    // ---- coalesced float4 staging of dW/dH (480 float4 each) ----------
    const float4* __restrict__ w4 = (const float4*)(dW + base * 15);
    const float4* __restrict__ h4 = (const float4*)(dH + base * 15);
    float4* sw4 = (float4*)s_w;
    float4* sh4 = (float4*)s_h;
#pragma unroll
    for (int i = 0; i < 3; i++) {
        sw4[tid + i * BLK] = __ldcs(&w4[tid + i * BLK]);
        sh4[tid + i * BLK] = __ldcs(&h4[tid + i * BLK]);
    }
    if (tid < 96) {                                  // 96 tail float4 each
        sw4[tid + 3 * BLK] = __ldcs(&w4[tid + 3 * BLK]);
        sh4[tid + 3 * BLK] = __ldcs(&h4[tid + 3 * BLK]);
    }

    // ---- x loaded directly: warp covers 384 contiguous bytes ----------
    float y0 = __ldcs(x + (base + tid) * 3 + 0);
    float y1 = __ldcs(x + (base + tid) * 3 + 1);
    float y2 = __ldcs(x + (base + tid) * 3 + 2);
    __syncthreads();

    const float dt    = 0.01f;
    const float cW    = 0.2f;            // NOISE * sqrt(dt)
    const float cH    = 0.057735026919f; // NOISE * sqrt(dt/12)
    const float c56dt = (5.0f / 6.0f) * 0.01f;
    const float c56   = 5.0f / 6.0f;

#pragma unroll
    for (int s = 0; s < NSTEP; s++) {
        const int wb = tid * (NSTEP * 3) + s * 3;    // stride 15: conflict-free
        float w0 = cW * s_w[wb + 0];
        float w1 = cW * s_w[wb + 1];
        float w2 = cW * s_w[wb + 2];
        float h0 = cH * s_h[wb + 0];
        float h1 = cH * s_h[wb + 1];
        float h2 = cH * s_h[wb + 2];

        // z1 = y + h
        float z0 = y0 + h0, z1 = y1 + h1, z2 = y2 + h2;
        float f10, f11, f12;
        lorenz_drift(z0, z1, z2, f10, f11, f12);

        // z2 = y + (5/6)dt*f1 + (5/6)*w + h
        float u0 = y0 + c56dt * f10 + c56 * w0 + h0;
        float u1 = y1 + c56dt * f11 + c56 * w1 + h1;
        float u2 = y2 + c56dt * f12 + c56 * w2 + h2;
        float f20, f21, f22;
        lorenz_drift(u0, u1, u2, f20, f21, f22);

        // y = y + dt*(0.4*f1 + 0.6*f2) + w
        y0 = y0 + dt * (0.4f * f10 + 0.6f * f20) + w0;
        y1 = y1 + dt * (0.4f * f11 + 0.6f * f21) + w1;
        y2 = y2 + dt * (0.4f * f12 + 0.6f * f22) + w2;
    }

    // ---- output staging into OWN exclusive s_w slots (tid*15+0..2):
    // no other thread ever reads these -> no barrier needed before write.
    s_w[tid * 15 + 0] = y0;
    s_w[tid * 15 + 1] = y1;
    s_w[tid * 15 + 2] = y2;
    __syncthreads();

    // ---- coalesced float4 store; gather from stride-15 layout ----------
    if (tid < 96) {                                  // 96 float4 = 384 floats
        float v[4];
#pragma unroll
        for (int j = 0; j < 4; j++) {
            int f = 4 * tid + j;                     // float index in tile out
            int e = f / 3;                           // element
            int c = f - e * 3;                       // component
            v[j] = s_w[e * 15 + c];
        }
        float4* o4 = (float4*)(out + base * 3);
        __stcs(&o4[tid], make_float4(v[0], v[1], v[2], v[3]));
    }
}

extern "C" void kernel_launch(void* const* d_in, const int* in_sizes, int n_in,
                              void* d_out, int out_size) {
    const float* x  = (const float*)d_in[0];   // [B, 3]
    const float* dW = (const float*)d_in[1];   // [B, 5, 3]
    const float* dH = (const float*)d_in[2];   // [B, 5, 3]
    float* out = (float*)d_out;                // [B, 3]

    lorenz_shark_kernel<<<NTILES, BLK>>>(x, dW, dH, out);
}

// round 16
// speedup vs baseline: 1.2234x; 1.0559x over previous
#include <cuda_runtime.h>
#include <cuda_bf16.h>
#include <cstdint>

// LorenzSDE ShARK integrator, B = 4,194,304, 5 steps, additive noise.
// HBM-bound streaming (604 MB) pinned at ~6.7 TB/s (~84.5% DRAM) across
// all healthy configs -> at the achievable DRAM ceiling. This round only
// DELETES work from the best kernel (R13):
//  - output written directly from registers (stride-3 __stcs; warp covers
//    384 contiguous B, write-coalescer emits full lines) -> no staging,
//    no epilogue barrier. Exactly ONE __syncthreads() remains.
//  - x loads hoisted before dW/dH staging (earliest issue slots).
// Proven config kept: 128-thr one-shot CTAs, 12/SM, 15.4KB smem (L1D~44KB),
// __ldcs streaming reads, stride-15 conflict-free smem consumption.

#define BATCH_TOTAL 4194304
#define NSTEP 5
#define TILE 128                       // batch elements per tile == threads
#define BLK 128
#define NTILES (BATCH_TOTAL / TILE)    // 32768

__device__ __forceinline__ void lorenz_drift(float x, float y, float z,
                                             float& fx, float& fy, float& fz) {
    fx = 10.0f * (y - x);
    fy = x * (28.0f - z) - y;
    fz = x * y - (8.0f / 3.0f) * z;
}

__global__ __launch_bounds__(BLK, 12)
void lorenz_shark_kernel(const float* __restrict__ x,
                         const float* __restrict__ dW,
                         const float* __restrict__ dH,
                         float* __restrict__ out) {
    __shared__ __align__(16) float s_w[TILE * 15];   // 7680 B
    __shared__ __align__(16) float s_h[TILE * 15];   // 7680 B

    const int tid = threadIdx.x;
    const size_t base = (size_t)blockIdx.x * TILE;

    // ---- x loaded directly, first: warp covers 384 contiguous bytes ----
    float y0 = __ldcs(x + (base + tid) * 3 + 0);
    float y1 = __ldcs(x + (base + tid) * 3 + 1);
    float y2 = __ldcs(x + (base + tid) * 3 + 2);

    // ---- coalesced float4 staging of dW/dH (480 float4 each) ----------
    const float4* __restrict__ w4 = (const float4*)(dW + base * 15);
    const float4* __restrict__ h4 = (const float4*)(dH + base * 15);
    float4* sw4 = (float4*)s_w;
    float4* sh4 = (float4*)s_h;
#pragma unroll
    for (int i = 0; i < 3; i++) {
        sw4[tid + i * BLK] = __ldcs(&w4[tid + i * BLK]);
        sh4[tid + i * BLK] = __ldcs(&h4[tid + i * BLK]);
    }
    if (tid < 96) {                                  // 96 tail float4 each
        sw4[tid + 3 * BLK] = __ldcs(&w4[tid + 3 * BLK]);
        sh4[tid + 3 * BLK] = __ldcs(&h4[tid + 3 * BLK]);
    }
    __syncthreads();                                 // the only barrier

    const float dt    = 0.01f;
    const float cW    = 0.2f;            // NOISE * sqrt(dt)
    const float cH    = 0.057735026919f; // NOISE * sqrt(dt/12)
    const float c56dt = (5.0f / 6.0f) * 0.01f;
    const float c56   = 5.0f / 6.0f;

#pragma unroll
    for (int s = 0; s < NSTEP; s++) {
        const int wb = tid * (NSTEP * 3) + s * 3;    // stride 15: conflict-free
        float w0 = cW * s_w[wb + 0];
        float w1 = cW * s_w[wb + 1];
        float w2 = cW * s_w[wb + 2];
        float h0 = cH * s_h[wb + 0];
        float h1 = cH * s_h[wb + 1];
        float h2 = cH * s_h[wb + 2];

        // z1 = y + h
        float z0 = y0 + h0, z1 = y1 + h1, z2 = y2 + h2;
        float f10, f11, f12;
        lorenz_drift(z0, z1, z2, f10, f11, f12);

        // z2 = y + (5/6)dt*f1 + (5/6)*w + h
        float u0 = y0 + c56dt * f10 + c56 * w0 + h0;
        float u1 = y1 + c56dt * f11 + c56 * w1 + h1;
        float u2 = y2 + c56dt * f12 + c56 * w2 + h2;
        float f20, f21, f22;
        lorenz_drift(u0, u1, u2, f20, f21, f22);

        // y = y + dt*(0.4*f1 + 0.6*f2) + w
        y0 = y0 + dt * (0.4f * f10 + 0.6f * f20) + w0;
        y1 = y1 + dt * (0.4f * f11 + 0.6f * f21) + w1;
        y2 = y2 + dt * (0.4f * f12 + 0.6f * f22) + w2;
    }

    // ---- direct store: 3 stride-3 STG.32 per thread; per warp these
    // cover 384 contiguous bytes -> write coalescer emits full lines.
    float* o = out + (base + tid) * 3;
    __stcs(o + 0, y0);
    __stcs(o + 1, y1);
    __stcs(o + 2, y2);
}

extern "C" void kernel_launch(void* const* d_in, const int* in_sizes, int n_in,
                              void* d_out, int out_size) {
    const float* x  = (const float*)d_in[0];   // [B, 3]
    const float* dW = (const float*)d_in[1];   // [B, 5, 3]
    const float* dH = (const float*)d_in[2];   // [B, 5, 3]
    float* out = (float*)d_out;                // [B, 3]

    lorenz_shark_kernel<<<NTILES, BLK>>>(x, dW, dH, out);
}